// round 8
// baseline (speedup 1.0000x reference)
#include <cuda_runtime.h>
#include <cuda_bf16.h>
#include <cstdint>

// Problem constants
#define BATCH 4
#define SEQ   2048
#define DM    1024
#define NH    16
#define HD    64
#define MROWS (BATCH*SEQ)          // 8192
#define NEGBIAS (-10000.0f)

// Scratch (no allocation allowed)
// bf16 hi/lo head-split projections [bh][t][hd]
__device__ __nv_bfloat16 g_qhi[BATCH*NH*SEQ*HD];
__device__ __nv_bfloat16 g_qlo[BATCH*NH*SEQ*HD];
__device__ __nv_bfloat16 g_khi[BATCH*NH*SEQ*HD];
__device__ __nv_bfloat16 g_klo[BATCH*NH*SEQ*HD];
__device__ __nv_bfloat16 g_vhi[BATCH*NH*SEQ*HD];
__device__ __nv_bfloat16 g_vlo[BATCH*NH*SEQ*HD];
// activation splits for q,k,v (slot 0 reused for ctx); weights Wq,Wk,Wv,Wo
__device__ __nv_bfloat16 g_xhi[3*MROWS*DM];
__device__ __nv_bfloat16 g_xlo[3*MROWS*DM];
__device__ __nv_bfloat16 g_whi[4*DM*DM];
__device__ __nv_bfloat16 g_wlo[4*DM*DM];

// ---------------------------------------------------------------------------
// helpers
// ---------------------------------------------------------------------------
__device__ __forceinline__ uint32_t smem_u32(const void* p) {
    uint32_t a;
    asm("{ .reg .u64 t; cvta.to.shared.u64 t, %1; cvt.u32.u64 %0, t; }" : "=r"(a) : "l"(p));
    return a;
}
#define SWZ128(o) ((uint32_t)(o) ^ ((((uint32_t)(o)) >> 3) & 0x70))

#define CP_ASYNC16(saddr, gptr) \
    asm volatile("cp.async.cg.shared.global [%0], [%1], 16;" :: "r"(saddr), "l"(gptr) : "memory")
#define CP_ASYNC4(saddr, gptr) \
    asm volatile("cp.async.ca.shared.global [%0], [%1], 4;" :: "r"(saddr), "l"(gptr) : "memory")
#define CP_COMMIT() asm volatile("cp.async.commit_group;" ::: "memory")
#define CP_WAIT1()  asm volatile("cp.async.wait_group 1;" ::: "memory")
#define CP_WAIT0()  asm volatile("cp.async.wait_group 0;" ::: "memory")

#define LDSM4(R0,R1,R2,R3,ADDR) \
    asm volatile("ldmatrix.sync.aligned.m8n8.x4.shared.b16 {%0,%1,%2,%3}, [%4];" \
        : "=r"(R0), "=r"(R1), "=r"(R2), "=r"(R3) : "r"(ADDR))
#define LDSM4T(R0,R1,R2,R3,ADDR) \
    asm volatile("ldmatrix.sync.aligned.m8n8.x4.trans.shared.b16 {%0,%1,%2,%3}, [%4];" \
        : "=r"(R0), "=r"(R1), "=r"(R2), "=r"(R3) : "r"(ADDR))

__device__ __forceinline__ void mma16816(float* c, const uint32_t* a,
                                         uint32_t b0, uint32_t b1) {
    asm volatile(
        "mma.sync.aligned.m16n8k16.row.col.f32.bf16.bf16.f32 "
        "{%0,%1,%2,%3}, {%4,%5,%6,%7}, {%8,%9}, {%0,%1,%2,%3};"
        : "+f"(c[0]), "+f"(c[1]), "+f"(c[2]), "+f"(c[3])
        : "r"(a[0]), "r"(a[1]), "r"(a[2]), "r"(a[3]), "r"(b0), "r"(b1));
}

__device__ __forceinline__ void split1(float v, uint16_t& hi, uint16_t& lo) {
    __nv_bfloat16 bh = __float2bfloat16(v);
    hi = __bfloat16_as_ushort(bh);
    lo = __bfloat16_as_ushort(__float2bfloat16(v - __bfloat162float(bh)));
}

// ---------------------------------------------------------------------------
// split kernels: fp32 -> bf16 hi + bf16 residual lo
// ---------------------------------------------------------------------------
__device__ __forceinline__ void split4(const float4* src, uint2* hi, uint2* lo, int i) {
    float4 v = src[i];
    float f[4] = {v.x, v.y, v.z, v.w};
    uint32_t h[4], l[4];
#pragma unroll
    for (int j = 0; j < 4; j++) {
        uint16_t hb, lb;
        split1(f[j], hb, lb);
        h[j] = hb; l[j] = lb;
    }
    hi[i] = make_uint2(h[0] | (h[1] << 16), h[2] | (h[3] << 16));
    lo[i] = make_uint2(l[0] | (l[1] << 16), l[2] | (l[3] << 16));
}

__global__ void __launch_bounds__(256)
split_acts(const float4* __restrict__ q, const float4* __restrict__ k,
           const float4* __restrict__ v)
{
    const int sel = blockIdx.y;
    const int n4  = MROWS * DM / 4;
    int i = blockIdx.x * 256 + threadIdx.x;
    if (i >= n4) return;
    const float4* src = (sel == 0) ? q : (sel == 1) ? k : v;
    uint2* hi = (uint2*)&g_xhi[(size_t)sel * MROWS * DM];
    uint2* lo = (uint2*)&g_xlo[(size_t)sel * MROWS * DM];
    split4(src, hi, lo, i);
}

__global__ void __launch_bounds__(256)
split_w(const float4* __restrict__ wq, const float4* __restrict__ wk,
        const float4* __restrict__ wv, const float4* __restrict__ wo)
{
    const int sel = blockIdx.y;
    const int n4  = DM * DM / 4;
    int i = blockIdx.x * 256 + threadIdx.x;
    if (i >= n4) return;
    const float4* src = (sel == 0) ? wq : (sel == 1) ? wk : (sel == 2) ? wv : wo;
    uint2* hi = (uint2*)&g_whi[(size_t)sel * DM * DM];
    uint2* lo = (uint2*)&g_wlo[(size_t)sel * DM * DM];
    split4(src, hi, lo, i);
}

// ---------------------------------------------------------------------------
// HMMA GEMM: out[m,n] = sum_k X[m,k]*W[n,k], X/W pre-split bf16 hi/lo.
// grid.z selects (X, W, output) slice. outf==nullptr -> headsplit bf16 hi/lo
// to g_{q,k,v}{hi,lo}; else f32 row-major to outf.
// 3-stage cp.async pipeline, single sync per iteration, loads before compute.
// ---------------------------------------------------------------------------
#define GT_TILE  16384
#define GT_STAGE (4*GT_TILE)
#define GSTAGES  3
#define GSMEM_BYTES (GSTAGES*GT_STAGE)   // 192 KB
#define NCHUNK 16                        // K=1024 / 64

__device__ __forceinline__ void g_load_stage(
    uint32_t sb, int stage,
    const __nv_bfloat16* __restrict__ Ahi, const __nv_bfloat16* __restrict__ Alo,
    const __nv_bfloat16* __restrict__ Bhi, const __nv_bfloat16* __restrict__ Blo,
    int m0, int n0, int k0, int t)
{
    const uint32_t base = sb + stage * GT_STAGE;
#pragma unroll
    for (int i = 0; i < 4; i++) {
        int tt  = t + 256 * i;
        int row = tt >> 3;
        int ch  = tt & 7;
        uint32_t soff = SWZ128(row * 128 + ch * 16);
        CP_ASYNC16(base + soff,             Ahi + (size_t)(m0 + row) * DM + k0 + ch * 8);
        CP_ASYNC16(base + GT_TILE + soff,   Alo + (size_t)(m0 + row) * DM + k0 + ch * 8);
        CP_ASYNC16(base + 2*GT_TILE + soff, Bhi + (size_t)(n0 + row) * DM + k0 + ch * 8);
        CP_ASYNC16(base + 3*GT_TILE + soff, Blo + (size_t)(n0 + row) * DM + k0 + ch * 8);
    }
    CP_COMMIT();
}

__global__ void __launch_bounds__(256)
gemm_hmma(const __nv_bfloat16* __restrict__ Ahi_, const __nv_bfloat16* __restrict__ Alo_,
          const __nv_bfloat16* __restrict__ Bhi_, const __nv_bfloat16* __restrict__ Blo_,
          float* __restrict__ outf)
{
    extern __shared__ char smem[];
    const uint32_t sb = smem_u32(smem);
    const int t   = threadIdx.x;
    const int wid = t >> 5, lid = t & 31;
    const int wm  = wid & 3;
    const int wn  = wid >> 2;
    const int m0  = blockIdx.y * 128;
    const int n0  = blockIdx.x * 128;
    const int z   = blockIdx.z;

    const __nv_bfloat16* Ahi = Ahi_ + (size_t)z * MROWS * DM;
    const __nv_bfloat16* Alo = Alo_ + (size_t)z * MROWS * DM;
    const __nv_bfloat16* Bhi = Bhi_ + (size_t)z * DM * DM;
    const __nv_bfloat16* Blo = Blo_ + (size_t)z * DM * DM;

    float acc[2][8][4];
#pragma unroll
    for (int a = 0; a < 2; a++)
#pragma unroll
        for (int b = 0; b < 8; b++)
#pragma unroll
            for (int c = 0; c < 4; c++) acc[a][b][c] = 0.0f;

    g_load_stage(sb, 0, Ahi, Alo, Bhi, Blo, m0, n0, 0,  t);
    g_load_stage(sb, 1, Ahi, Alo, Bhi, Blo, m0, n0, 64, t);

    for (int c = 0; c < NCHUNK; c++) {
        if (c < NCHUNK - 1) { CP_WAIT1(); } else { CP_WAIT0(); }
        __syncthreads();
        // prefetch chunk c+2 into stage (c+2)%3 (read last at iter c-1; safe after sync)
        if (c + 2 < NCHUNK)
            g_load_stage(sb, (c + 2) % GSTAGES, Ahi, Alo, Bhi, Blo, m0, n0, (c + 2) * 64, t);

        const uint32_t st = sb + (c % GSTAGES) * GT_STAGE;
#pragma unroll
        for (int ks = 0; ks < 4; ks++) {
            const int colb = ks * 32 + ((lid >> 4) << 4);
            uint32_t ah[2][4], al[2][4];
#pragma unroll
            for (int mt = 0; mt < 2; mt++) {
                int row = wm * 32 + mt * 16 + (lid & 15);
                uint32_t off = SWZ128(row * 128 + colb);
                LDSM4(ah[mt][0], ah[mt][1], ah[mt][2], ah[mt][3], st + off);
                LDSM4(al[mt][0], al[mt][1], al[mt][2], al[mt][3], st + GT_TILE + off);
            }
            uint32_t bh[4][4], bl[4][4];
#pragma unroll
            for (int np = 0; np < 4; np++) {
                int row = wn * 64 + np * 16 + (lid & 15);
                uint32_t off = SWZ128(row * 128 + colb);
                LDSM4(bh[np][0], bh[np][1], bh[np][2], bh[np][3], st + 2*GT_TILE + off);
                LDSM4(bl[np][0], bl[np][1], bl[np][2], bl[np][3], st + 3*GT_TILE + off);
            }
#pragma unroll
            for (int mt = 0; mt < 2; mt++) {
#pragma unroll
                for (int np = 0; np < 4; np++) {
                    mma16816(acc[mt][2*np],   ah[mt], bh[np][0], bh[np][2]);
                    mma16816(acc[mt][2*np],   ah[mt], bl[np][0], bl[np][2]);
                    mma16816(acc[mt][2*np],   al[mt], bh[np][0], bh[np][2]);
                    mma16816(acc[mt][2*np+1], ah[mt], bh[np][1], bh[np][3]);
                    mma16816(acc[mt][2*np+1], ah[mt], bl[np][1], bl[np][3]);
                    mma16816(acc[mt][2*np+1], al[mt], bh[np][1], bh[np][3]);
                }
            }
        }
    }

    // epilogue
    __nv_bfloat16* ohi = nullptr;
    __nv_bfloat16* olo = nullptr;
    if (!outf) {
        ohi = (z == 0) ? g_qhi : (z == 1) ? g_khi : g_vhi;
        olo = (z == 0) ? g_qlo : (z == 1) ? g_klo : g_vlo;
    }
#pragma unroll
    for (int mt = 0; mt < 2; mt++) {
#pragma unroll
        for (int nt = 0; nt < 8; nt++) {
            int row0 = m0 + wm * 32 + mt * 16 + (lid >> 2);
            int col  = n0 + wn * 64 + nt * 8 + (lid & 3) * 2;
#pragma unroll
            for (int half = 0; half < 2; half++) {
                int row = row0 + half * 8;
                float vx = acc[mt][nt][half * 2 + 0];
                float vy = acc[mt][nt][half * 2 + 1];
                if (!outf) {
                    int bb = row >> 11, tt2 = row & 2047;
                    int h = col >> 6, dh = col & 63;
                    size_t base = ((((size_t)bb * NH + h) * SEQ) + tt2) * HD + dh;
                    uint16_t hx, lx, hy, ly;
                    split1(vx, hx, lx);
                    split1(vy, hy, ly);
                    *(uint32_t*)&ohi[base] = (uint32_t)hx | ((uint32_t)hy << 16);
                    *(uint32_t*)&olo[base] = (uint32_t)lx | ((uint32_t)ly << 16);
                } else {
                    float2 v2; v2.x = vx; v2.y = vy;
                    *(float2*)&outf[(size_t)row * DM + col] = v2;
                }
            }
        }
    }
}

// ---------------------------------------------------------------------------
// HMMA flash attention. CTA = (b,h) x 128 q rows, 8 warps x 16 rows.
// K-tile 64, 3-stage cp.async pipeline, single sync/iter, loads before compute.
// Longest-first qt order for causal wave balance.
// smem: Qhi 16K | Qlo 16K | 3 stages x 32K (Khi|Klo|Vhi|Vlo 8K each) | 3x256 mask
// ---------------------------------------------------------------------------
#define AT_KT   64
#define AT_Q    32768
#define AT_STGB 32768
#define AT_STAGES 3
#define AT_MSK  (AT_Q + AT_STAGES*AT_STGB)   // 131072
#define ATTN_SMEM_BYTES (AT_MSK + AT_STAGES*256)

__device__ __forceinline__ void a_load_stage(
    uint32_t sb, int stage,
    const __nv_bfloat16* Khi, const __nv_bfloat16* Klo,
    const __nv_bfloat16* Vhi, const __nv_bfloat16* Vlo,
    const float* amaskb, int kt0, int t)
{
    const uint32_t base = sb + AT_Q + stage * AT_STGB;
#pragma unroll
    for (int i = 0; i < 8; i++) {
        int chunk = t + 256 * i;            // 0..2047
        int tsel  = chunk >> 9;             // 0..3
        int c     = chunk & 511;
        int row   = c >> 3;
        int ch    = c & 7;
        uint32_t soff = (uint32_t)tsel * 8192 + SWZ128(row * 128 + ch * 16);
        const __nv_bfloat16* src =
            (tsel == 0) ? Khi : (tsel == 1) ? Klo : (tsel == 2) ? Vhi : Vlo;
        CP_ASYNC16(base + soff, src + (size_t)(kt0 + row) * HD + ch * 8);
    }
    if (t < AT_KT)
        CP_ASYNC4(sb + AT_MSK + stage * 256 + t * 4, amaskb + kt0 + t);
    CP_COMMIT();
}

__global__ void __launch_bounds__(256)
attn_hmma(const float* __restrict__ amask, const int* __restrict__ mask_future)
{
    extern __shared__ char smem[];
    const uint32_t sb = smem_u32(smem);
    const int t   = threadIdx.x;
    const int wid = t >> 5, lid = t & 31;
    const int bh  = blockIdx.y;
    const int b   = bh >> 4;
    const int h   = bh & 15;
    const int qt  = gridDim.x - 1 - blockIdx.x;   // longest tiles first
    const int m0w = wid * 16;

    const size_t bhoff = (size_t)bh * SEQ * HD;
    const __nv_bfloat16* Qhi = g_qhi + bhoff;
    const __nv_bfloat16* Qlo = g_qlo + bhoff;
    const __nv_bfloat16* Khi = g_khi + bhoff;
    const __nv_bfloat16* Klo = g_klo + bhoff;
    const __nv_bfloat16* Vhi = g_vhi + bhoff;
    const __nv_bfloat16* Vlo = g_vlo + bhoff;
    const float* amaskb = amask + (size_t)b * SEQ;

    // Q hi/lo (128x64 bf16, SW128); joins stage-0's commit group
#pragma unroll
    for (int i = 0; i < 4; i++) {
        int chunk = t + 256 * i;
        int row   = chunk >> 3;
        int ch    = chunk & 7;
        uint32_t soff = SWZ128(row * 128 + ch * 16);
        CP_ASYNC16(sb + soff,         Qhi + (size_t)(qt*128 + row) * HD + ch * 8);
        CP_ASYNC16(sb + 16384 + soff, Qlo + (size_t)(qt*128 + row) * HD + ch * 8);
    }
    const int causal = mask_future[0] != 0;
    const int ntiles = causal ? (qt * 2 + 2) : (SEQ / AT_KT);
    const int nfull  = causal ? (qt * 2)     : ntiles;

    a_load_stage(sb, 0, Khi, Klo, Vhi, Vlo, amaskb, 0, t);
    a_load_stage(sb, 1, Khi, Klo, Vhi, Vlo, amaskb, AT_KT, t);

    const int r1 = lid >> 2;
    const int gq1 = qt*128 + m0w + r1;
    const int gq2 = gq1 + 8;
    const int cq  = (lid & 3) * 2;

    float m1 = -1e30f, m2 = -1e30f, l1 = 0.0f, l2 = 0.0f;
    float O[8][4];
#pragma unroll
    for (int i = 0; i < 8; i++)
#pragma unroll
        for (int j = 0; j < 4; j++) O[i][j] = 0.0f;

    for (int kt = 0; kt < ntiles; kt++) {
        if (kt < ntiles - 1) { CP_WAIT1(); } else { CP_WAIT0(); }
        __syncthreads();
        // prefetch tile kt+2 into stage (kt+2)%3 (read last at iter kt-1)
        if (kt + 2 < ntiles)
            a_load_stage(sb, (kt + 2) % AT_STAGES, Khi, Klo, Vhi, Vlo, amaskb,
                         (kt + 2) * AT_KT, t);

        const uint32_t st  = sb + AT_Q + (kt % AT_STAGES) * AT_STGB;
        const uint32_t msk = sb + AT_MSK + (kt % AT_STAGES) * 256;

        // ---- S = Q K^T (hi/lo 3-product) ----
        float S[8][4];
#pragma unroll
        for (int i = 0; i < 8; i++)
#pragma unroll
            for (int j = 0; j < 4; j++) S[i][j] = 0.0f;

#pragma unroll
        for (int k16 = 0; k16 < 4; k16++) {
            const int colb = k16 * 32 + (lid >> 4) * 16;
            uint32_t qh_[4], ql_[4];
            {
                int row = m0w + (lid & 15);
                uint32_t off = SWZ128(row * 128 + colb);
                LDSM4(qh_[0], qh_[1], qh_[2], qh_[3], sb + off);
                LDSM4(ql_[0], ql_[1], ql_[2], ql_[3], sb + 16384 + off);
            }
#pragma unroll
            for (int np = 0; np < 4; np++) {
                int row = np * 16 + (lid & 15);
                uint32_t off = SWZ128(row * 128 + colb);
                uint32_t kh_[4], kl_[4];
                LDSM4(kh_[0], kh_[1], kh_[2], kh_[3], st + off);
                LDSM4(kl_[0], kl_[1], kl_[2], kl_[3], st + 8192 + off);
                mma16816(S[2*np],   qh_, kh_[0], kh_[2]);
                mma16816(S[2*np],   qh_, kl_[0], kl_[2]);
                mma16816(S[2*np],   ql_, kh_[0], kh_[2]);
                mma16816(S[2*np+1], qh_, kh_[1], kh_[3]);
                mma16816(S[2*np+1], qh_, kl_[1], kl_[3]);
                mma16816(S[2*np+1], ql_, kh_[1], kh_[3]);
            }
        }

        // ---- scale + masks ----
        const int diag = (kt >= nfull);
#pragma unroll
        for (int nt = 0; nt < 8; nt++) {
            int jl0 = nt * 8 + cq;
            float p0, p1;
            asm("ld.shared.f32 %0, [%1];" : "=f"(p0) : "r"(msk + jl0 * 4));
            asm("ld.shared.f32 %0, [%1];" : "=f"(p1) : "r"(msk + jl0 * 4 + 4));
            int gk0 = kt * AT_KT + jl0;
#pragma unroll
            for (int c = 0; c < 4; c++) {
                float sv = S[nt][c] * 0.125f;
                int gk = gk0 + (c & 1);
                int gq = (c < 2) ? gq1 : gq2;
                if (diag && gk > gq) sv += NEGBIAS;
                float pm = (c & 1) ? p1 : p0;
                if (pm == 0.0f) sv = NEGBIAS;
                S[nt][c] = sv;
            }
        }

        // ---- online softmax ----
        float t1 = -1e30f, t2 = -1e30f;
#pragma unroll
        for (int nt = 0; nt < 8; nt++) {
            t1 = fmaxf(t1, fmaxf(S[nt][0], S[nt][1]));
            t2 = fmaxf(t2, fmaxf(S[nt][2], S[nt][3]));
        }
        t1 = fmaxf(t1, __shfl_xor_sync(0xffffffffu, t1, 1));
        t1 = fmaxf(t1, __shfl_xor_sync(0xffffffffu, t1, 2));
        t2 = fmaxf(t2, __shfl_xor_sync(0xffffffffu, t2, 1));
        t2 = fmaxf(t2, __shfl_xor_sync(0xffffffffu, t2, 2));
        float mn1 = fmaxf(m1, t1), mn2 = fmaxf(m2, t2);
        float corr1 = __expf(m1 - mn1), corr2 = __expf(m2 - mn2);
        m1 = mn1; m2 = mn2;
        l1 *= corr1; l2 *= corr2;

        uint32_t phi[4][4], plo[4][4];
#pragma unroll
        for (int nt2 = 0; nt2 < 4; nt2++) {
#pragma unroll
            for (int half = 0; half < 2; half++) {
                int nt = 2*nt2 + half;
                float e0 = __expf(S[nt][0] - mn1);
                float e1 = __expf(S[nt][1] - mn1);
                float e2 = __expf(S[nt][2] - mn2);
                float e3 = __expf(S[nt][3] - mn2);
                l1 += e0 + e1; l2 += e2 + e3;
                uint16_t hh0, ll0, hh1, ll1, hh2, ll2, hh3, ll3;
                split1(e0, hh0, ll0); split1(e1, hh1, ll1);
                split1(e2, hh2, ll2); split1(e3, hh3, ll3);
                phi[nt2][2*half]   = (uint32_t)hh0 | ((uint32_t)hh1 << 16);
                phi[nt2][2*half+1] = (uint32_t)hh2 | ((uint32_t)hh3 << 16);
                plo[nt2][2*half]   = (uint32_t)ll0 | ((uint32_t)ll1 << 16);
                plo[nt2][2*half+1] = (uint32_t)ll2 | ((uint32_t)ll3 << 16);
            }
        }

        // rescale O
#pragma unroll
        for (int i = 0; i < 8; i++) {
            O[i][0] *= corr1; O[i][1] *= corr1;
            O[i][2] *= corr2; O[i][3] *= corr2;
        }

        // ---- O += P V (hi/lo 3-product) ----
        const uint32_t vbase_hi = st + 16384, vbase_lo = st + 24576;
#pragma unroll
        for (int hdb = 0; hdb < 4; hdb++) {
#pragma unroll
            for (int k16 = 0; k16 < 4; k16++) {
                int row  = k16 * 16 + (lid & 7) + ((lid >> 3) & 1) * 8;
                int colb = hdb * 32 + (lid >> 4) * 16;
                uint32_t off = SWZ128(row * 128 + colb);
                uint32_t vh_[4], vl_[4];
                LDSM4T(vh_[0], vh_[1], vh_[2], vh_[3], vbase_hi + off);
                LDSM4T(vl_[0], vl_[1], vl_[2], vl_[3], vbase_lo + off);
                mma16816(O[2*hdb],   phi[k16], vh_[0], vh_[1]);
                mma16816(O[2*hdb],   phi[k16], vl_[0], vl_[1]);
                mma16816(O[2*hdb],   plo[k16], vh_[0], vh_[1]);
                mma16816(O[2*hdb+1], phi[k16], vh_[2], vh_[3]);
                mma16816(O[2*hdb+1], phi[k16], vl_[2], vl_[3]);
                mma16816(O[2*hdb+1], plo[k16], vh_[2], vh_[3]);
            }
        }
    }

    // finalize l across quad
    l1 += __shfl_xor_sync(0xffffffffu, l1, 1);
    l1 += __shfl_xor_sync(0xffffffffu, l1, 2);
    l2 += __shfl_xor_sync(0xffffffffu, l2, 1);
    l2 += __shfl_xor_sync(0xffffffffu, l2, 2);
    float rl1 = 1.0f / l1, rl2 = 1.0f / l2;

    // write ctx hi/lo into activation slot 0: [b*T+t][h*64+hd]
    const size_t rowb1 = ((size_t)b * SEQ + gq1) * DM + h * HD;
    const size_t rowb2 = ((size_t)b * SEQ + gq2) * DM + h * HD;
#pragma unroll
    for (int nt = 0; nt < 8; nt++) {
        int col = nt * 8 + cq;
        float v0 = O[nt][0] * rl1, v1 = O[nt][1] * rl1;
        float v2 = O[nt][2] * rl2, v3 = O[nt][3] * rl2;
        uint16_t h0, l0, h1b, l1b, h2, l2b, h3, l3;
        split1(v0, h0, l0); split1(v1, h1b, l1b);
        split1(v2, h2, l2b); split1(v3, h3, l3);
        *(uint32_t*)&g_xhi[rowb1 + col] = (uint32_t)h0 | ((uint32_t)h1b << 16);
        *(uint32_t*)&g_xlo[rowb1 + col] = (uint32_t)l0 | ((uint32_t)l1b << 16);
        *(uint32_t*)&g_xhi[rowb2 + col] = (uint32_t)h2 | ((uint32_t)h3 << 16);
        *(uint32_t*)&g_xlo[rowb2 + col] = (uint32_t)l2b | ((uint32_t)l3 << 16);
    }
}

// ---------------------------------------------------------------------------
extern "C" void kernel_launch(void* const* d_in, const int* in_sizes, int n_in,
                              void* d_out, int out_size)
{
    const float* q  = (const float*)d_in[0];
    const float* k  = (const float*)d_in[1];
    const float* v  = (const float*)d_in[2];
    const float* am = (const float*)d_in[3];
    const float* Wq = (const float*)d_in[4];
    const float* Wk = (const float*)d_in[5];
    const float* Wv = (const float*)d_in[6];
    const float* Wo = (const float*)d_in[7];
    const int*   mf = (const int*)  d_in[8];
    float* out = (float*)d_out;

    __nv_bfloat16 *xhi, *xlo, *whi, *wlo;
    cudaGetSymbolAddress((void**)&xhi, g_xhi);
    cudaGetSymbolAddress((void**)&xlo, g_xlo);
    cudaGetSymbolAddress((void**)&whi, g_whi);
    cudaGetSymbolAddress((void**)&wlo, g_wlo);

    static bool attr_set = false;
    if (!attr_set) {
        cudaFuncSetAttribute(gemm_hmma,
                             cudaFuncAttributeMaxDynamicSharedMemorySize, GSMEM_BYTES);
        cudaFuncSetAttribute(attn_hmma,
                             cudaFuncAttributeMaxDynamicSharedMemorySize, ATTN_SMEM_BYTES);
        attr_set = true;
    }

    // splits: 2 launches
    split_acts<<<dim3(MROWS*DM/4/256, 3), 256>>>((const float4*)q, (const float4*)k,
                                                 (const float4*)v);
    split_w<<<dim3(DM*DM/4/256, 4), 256>>>((const float4*)Wq, (const float4*)Wk,
                                           (const float4*)Wv, (const float4*)Wo);

    // fused Q/K/V projections (grid.z = 3)
    gemm_hmma<<<dim3(DM/128, MROWS/128, 3), 256, GSMEM_BYTES>>>(
        xhi, xlo, whi, wlo, nullptr);

    // attention (writes ctx hi/lo into activation slot 0)
    attn_hmma<<<dim3(SEQ/128, BATCH*NH), 256, ATTN_SMEM_BYTES>>>(am, mf);

    // output projection (z = 0; weight slot 3)
    gemm_hmma<<<dim3(DM/128, MROWS/128, 1), 256, GSMEM_BYTES>>>(
        xhi, xlo, whi + (size_t)3*DM*DM, wlo + (size_t)3*DM*DM, out);
}

// round 10
// speedup vs baseline: 1.0637x; 1.0637x over previous
#include <cuda_runtime.h>
#include <cuda_bf16.h>
#include <cstdint>

// Problem constants
#define BATCH 4
#define SEQ   2048
#define DM    1024
#define NH    16
#define HD    64
#define MROWS (BATCH*SEQ)          // 8192
#define NEGBIAS (-10000.0f)

// Scratch (no allocation allowed)
__device__ __nv_bfloat16 g_qhi[BATCH*NH*SEQ*HD];
__device__ __nv_bfloat16 g_qlo[BATCH*NH*SEQ*HD];
__device__ __nv_bfloat16 g_khi[BATCH*NH*SEQ*HD];
__device__ __nv_bfloat16 g_klo[BATCH*NH*SEQ*HD];
__device__ __nv_bfloat16 g_vhi[BATCH*NH*SEQ*HD];
__device__ __nv_bfloat16 g_vlo[BATCH*NH*SEQ*HD];
__device__ __nv_bfloat16 g_xhi[3*MROWS*DM];
__device__ __nv_bfloat16 g_xlo[3*MROWS*DM];
__device__ __nv_bfloat16 g_whi[4*DM*DM];
__device__ __nv_bfloat16 g_wlo[4*DM*DM];

// ---------------------------------------------------------------------------
// helpers
// ---------------------------------------------------------------------------
__device__ __forceinline__ uint32_t smem_u32(const void* p) {
    uint32_t a;
    asm("{ .reg .u64 t; cvta.to.shared.u64 t, %1; cvt.u32.u64 %0, t; }" : "=r"(a) : "l"(p));
    return a;
}
#define SWZ128(o) ((uint32_t)(o) ^ ((((uint32_t)(o)) >> 3) & 0x70))

#define CP_ASYNC16(saddr, gptr) \
    asm volatile("cp.async.cg.shared.global [%0], [%1], 16;" :: "r"(saddr), "l"(gptr) : "memory")
#define CP_ASYNC4(saddr, gptr) \
    asm volatile("cp.async.ca.shared.global [%0], [%1], 4;" :: "r"(saddr), "l"(gptr) : "memory")
#define CP_COMMIT() asm volatile("cp.async.commit_group;" ::: "memory")
#define CP_WAIT1()  asm volatile("cp.async.wait_group 1;" ::: "memory")
#define CP_WAIT0()  asm volatile("cp.async.wait_group 0;" ::: "memory")

#define LDSM4(R0,R1,R2,R3,ADDR) \
    asm volatile("ldmatrix.sync.aligned.m8n8.x4.shared.b16 {%0,%1,%2,%3}, [%4];" \
        : "=r"(R0), "=r"(R1), "=r"(R2), "=r"(R3) : "r"(ADDR))
#define LDSM4T(R0,R1,R2,R3,ADDR) \
    asm volatile("ldmatrix.sync.aligned.m8n8.x4.trans.shared.b16 {%0,%1,%2,%3}, [%4];" \
        : "=r"(R0), "=r"(R1), "=r"(R2), "=r"(R3) : "r"(ADDR))

__device__ __forceinline__ void mma16816(float* c, const uint32_t* a,
                                         uint32_t b0, uint32_t b1) {
    asm volatile(
        "mma.sync.aligned.m16n8k16.row.col.f32.bf16.bf16.f32 "
        "{%0,%1,%2,%3}, {%4,%5,%6,%7}, {%8,%9}, {%0,%1,%2,%3};"
        : "+f"(c[0]), "+f"(c[1]), "+f"(c[2]), "+f"(c[3])
        : "r"(a[0]), "r"(a[1]), "r"(a[2]), "r"(a[3]), "r"(b0), "r"(b1));
}

__device__ __forceinline__ void split1(float v, uint16_t& hi, uint16_t& lo) {
    __nv_bfloat16 bh = __float2bfloat16(v);
    hi = __bfloat16_as_ushort(bh);
    lo = __bfloat16_as_ushort(__float2bfloat16(v - __bfloat162float(bh)));
}

// ---------------------------------------------------------------------------
// split kernels
// ---------------------------------------------------------------------------
__device__ __forceinline__ void split4(const float4* src, uint2* hi, uint2* lo, int i) {
    float4 v = src[i];
    float f[4] = {v.x, v.y, v.z, v.w};
    uint32_t h[4], l[4];
#pragma unroll
    for (int j = 0; j < 4; j++) {
        uint16_t hb, lb;
        split1(f[j], hb, lb);
        h[j] = hb; l[j] = lb;
    }
    hi[i] = make_uint2(h[0] | (h[1] << 16), h[2] | (h[3] << 16));
    lo[i] = make_uint2(l[0] | (l[1] << 16), l[2] | (l[3] << 16));
}

__global__ void __launch_bounds__(256)
split_acts(const float4* __restrict__ q, const float4* __restrict__ k,
           const float4* __restrict__ v)
{
    const int sel = blockIdx.y;
    const int n4  = MROWS * DM / 4;
    int i = blockIdx.x * 256 + threadIdx.x;
    if (i >= n4) return;
    const float4* src = (sel == 0) ? q : (sel == 1) ? k : v;
    uint2* hi = (uint2*)&g_xhi[(size_t)sel * MROWS * DM];
    uint2* lo = (uint2*)&g_xlo[(size_t)sel * MROWS * DM];
    split4(src, hi, lo, i);
}

__global__ void __launch_bounds__(256)
split_w(const float4* __restrict__ wq, const float4* __restrict__ wk,
        const float4* __restrict__ wv, const float4* __restrict__ wo)
{
    const int sel = blockIdx.y;
    const int n4  = DM * DM / 4;
    int i = blockIdx.x * 256 + threadIdx.x;
    if (i >= n4) return;
    const float4* src = (sel == 0) ? wq : (sel == 1) ? wk : (sel == 2) ? wv : wo;
    uint2* hi = (uint2*)&g_whi[(size_t)sel * DM * DM];
    uint2* lo = (uint2*)&g_wlo[(size_t)sel * DM * DM];
    split4(src, hi, lo, i);
}

// ---------------------------------------------------------------------------
// HMMA GEMM, BK=32, hi|lo packed in 128-byte smem rows, 3 stages (96 KB),
// 2 CTAs/SM. Stage layout: [0,16K) A rows: [Ahi 64B | Alo 64B] per row;
// [16K,32K) B likewise.
// ---------------------------------------------------------------------------
#define GT_STAGE 32768
#define GSTAGES  3
#define GSMEM_BYTES (GSTAGES*GT_STAGE)   // 96 KB
#define NCHUNK 32                        // K=1024 / 32

__device__ __forceinline__ void g_load_stage(
    uint32_t sb, int stage,
    const __nv_bfloat16* __restrict__ Ahi, const __nv_bfloat16* __restrict__ Alo,
    const __nv_bfloat16* __restrict__ Bhi, const __nv_bfloat16* __restrict__ Blo,
    int m0, int n0, int k0, int t)
{
    const uint32_t base = sb + stage * GT_STAGE;
#pragma unroll
    for (int i = 0; i < 8; i++) {
        int idx = t + 256 * i;              // 0..2047
        int mat = idx >> 10;                // 0=A, 1=B
        int r   = (idx >> 3) & 127;
        int c   = idx & 7;                  // 0-3 hi, 4-7 lo
        uint32_t soff = (uint32_t)mat * 16384 + SWZ128(r * 128 + c * 16);
        const __nv_bfloat16* src;
        int gcol = k0 + (c & 3) * 8;
        if (mat == 0) src = ((c < 4) ? Ahi : Alo) + (size_t)(m0 + r) * DM + gcol;
        else          src = ((c < 4) ? Bhi : Blo) + (size_t)(n0 + r) * DM + gcol;
        CP_ASYNC16(base + soff, src);
    }
    CP_COMMIT();
}

__global__ void __launch_bounds__(256, 2)
gemm_hmma(const __nv_bfloat16* __restrict__ Ahi_, const __nv_bfloat16* __restrict__ Alo_,
          const __nv_bfloat16* __restrict__ Bhi_, const __nv_bfloat16* __restrict__ Blo_,
          float* __restrict__ outf)
{
    extern __shared__ char smem[];
    const uint32_t sb = smem_u32(smem);
    const int t   = threadIdx.x;
    const int wid = t >> 5, lid = t & 31;
    const int wm  = wid & 3;
    const int wn  = wid >> 2;
    const int m0  = blockIdx.y * 128;
    const int n0  = blockIdx.x * 128;
    const int z   = blockIdx.z;

    const __nv_bfloat16* Ahi = Ahi_ + (size_t)z * MROWS * DM;
    const __nv_bfloat16* Alo = Alo_ + (size_t)z * MROWS * DM;
    const __nv_bfloat16* Bhi = Bhi_ + (size_t)z * DM * DM;
    const __nv_bfloat16* Blo = Blo_ + (size_t)z * DM * DM;

    float acc[2][8][4];
#pragma unroll
    for (int a = 0; a < 2; a++)
#pragma unroll
        for (int b = 0; b < 8; b++)
#pragma unroll
            for (int c = 0; c < 4; c++) acc[a][b][c] = 0.0f;

    g_load_stage(sb, 0, Ahi, Alo, Bhi, Blo, m0, n0, 0,  t);
    g_load_stage(sb, 1, Ahi, Alo, Bhi, Blo, m0, n0, 32, t);

    for (int c = 0; c < NCHUNK; c++) {
        if (c < NCHUNK - 1) { CP_WAIT1(); } else { CP_WAIT0(); }
        __syncthreads();
        if (c + 2 < NCHUNK)
            g_load_stage(sb, (c + 2) % GSTAGES, Ahi, Alo, Bhi, Blo, m0, n0, (c + 2) * 32, t);

        const uint32_t st = sb + (c % GSTAGES) * GT_STAGE;
#pragma unroll
        for (int ks = 0; ks < 2; ks++) {
            const int cb = ks * 32 + ((lid >> 4) << 4);   // byte col (hi half)
            uint32_t ah[2][4], al[2][4];
#pragma unroll
            for (int mt = 0; mt < 2; mt++) {
                int row = wm * 32 + mt * 16 + (lid & 15);
                LDSM4(ah[mt][0], ah[mt][1], ah[mt][2], ah[mt][3],
                      st + SWZ128(row * 128 + cb));
                LDSM4(al[mt][0], al[mt][1], al[mt][2], al[mt][3],
                      st + SWZ128(row * 128 + 64 + cb));
            }
#pragma unroll
            for (int np = 0; np < 4; np++) {
                int row = wn * 64 + np * 16 + (lid & 15);
                uint32_t bh[4], bl[4];
                LDSM4(bh[0], bh[1], bh[2], bh[3], st + 16384 + SWZ128(row * 128 + cb));
                LDSM4(bl[0], bl[1], bl[2], bl[3], st + 16384 + SWZ128(row * 128 + 64 + cb));
#pragma unroll
                for (int mt = 0; mt < 2; mt++) {
                    mma16816(acc[mt][2*np],   ah[mt], bh[0], bh[2]);
                    mma16816(acc[mt][2*np],   ah[mt], bl[0], bl[2]);
                    mma16816(acc[mt][2*np],   al[mt], bh[0], bh[2]);
                    mma16816(acc[mt][2*np+1], ah[mt], bh[1], bh[3]);
                    mma16816(acc[mt][2*np+1], ah[mt], bl[1], bl[3]);
                    mma16816(acc[mt][2*np+1], al[mt], bh[1], bh[3]);
                }
            }
        }
    }

    // epilogue
    __nv_bfloat16* ohi = nullptr;
    __nv_bfloat16* olo = nullptr;
    if (!outf) {
        ohi = (z == 0) ? g_qhi : (z == 1) ? g_khi : g_vhi;
        olo = (z == 0) ? g_qlo : (z == 1) ? g_klo : g_vlo;
    }
#pragma unroll
    for (int mt = 0; mt < 2; mt++) {
#pragma unroll
        for (int nt = 0; nt < 8; nt++) {
            int row0 = m0 + wm * 32 + mt * 16 + (lid >> 2);
            int col  = n0 + wn * 64 + nt * 8 + (lid & 3) * 2;
#pragma unroll
            for (int half = 0; half < 2; half++) {
                int row = row0 + half * 8;
                float vx = acc[mt][nt][half * 2 + 0];
                float vy = acc[mt][nt][half * 2 + 1];
                if (!outf) {
                    int bb = row >> 11, tt2 = row & 2047;
                    int h = col >> 6, dh = col & 63;
                    size_t base = ((((size_t)bb * NH + h) * SEQ) + tt2) * HD + dh;
                    uint16_t hx, lx, hy, ly;
                    split1(vx, hx, lx);
                    split1(vy, hy, ly);
                    *(uint32_t*)&ohi[base] = (uint32_t)hx | ((uint32_t)hy << 16);
                    *(uint32_t*)&olo[base] = (uint32_t)lx | ((uint32_t)ly << 16);
                } else {
                    float2 v2; v2.x = vx; v2.y = vy;
                    *(float2*)&outf[(size_t)row * DM + col] = v2;
                }
            }
        }
    }
}

// ---------------------------------------------------------------------------
// HMMA flash attention. 2-stage pipeline (98.8 KB smem -> 2 CTAs/SM).
// CTA = (b,h) x 128 q rows, 8 warps x 16 rows; longest-first causal order.
// ---------------------------------------------------------------------------
#define AT_KT   64
#define AT_Q    32768
#define AT_STGB 32768
#define AT_MSK  (AT_Q + 2*AT_STGB)      // 98304
#define ATTN_SMEM_BYTES (AT_MSK + 512)

__device__ __forceinline__ void a_load_stage(
    uint32_t sb, int stage,
    const __nv_bfloat16* Khi, const __nv_bfloat16* Klo,
    const __nv_bfloat16* Vhi, const __nv_bfloat16* Vlo,
    const float* amaskb, int kt0, int t)
{
    const uint32_t base = sb + AT_Q + stage * AT_STGB;
#pragma unroll
    for (int i = 0; i < 8; i++) {
        int chunk = t + 256 * i;            // 0..2047
        int tsel  = chunk >> 9;             // 0..3
        int c     = chunk & 511;
        int row   = c >> 3;
        int ch    = c & 7;
        uint32_t soff = (uint32_t)tsel * 8192 + SWZ128(row * 128 + ch * 16);
        const __nv_bfloat16* src =
            (tsel == 0) ? Khi : (tsel == 1) ? Klo : (tsel == 2) ? Vhi : Vlo;
        CP_ASYNC16(base + soff, src + (size_t)(kt0 + row) * HD + ch * 8);
    }
    if (t < AT_KT)
        CP_ASYNC4(sb + AT_MSK + stage * 256 + t * 4, amaskb + kt0 + t);
    CP_COMMIT();
}

__global__ void __launch_bounds__(256, 2)
attn_hmma(const float* __restrict__ amask, const int* __restrict__ mask_future)
{
    extern __shared__ char smem[];
    const uint32_t sb = smem_u32(smem);
    const int t   = threadIdx.x;
    const int wid = t >> 5, lid = t & 31;
    const int bh  = blockIdx.y;
    const int b   = bh >> 4;
    const int h   = bh & 15;
    const int qt  = gridDim.x - 1 - blockIdx.x;   // longest tiles first
    const int m0w = wid * 16;

    const size_t bhoff = (size_t)bh * SEQ * HD;
    const __nv_bfloat16* Qhi = g_qhi + bhoff;
    const __nv_bfloat16* Qlo = g_qlo + bhoff;
    const __nv_bfloat16* Khi = g_khi + bhoff;
    const __nv_bfloat16* Klo = g_klo + bhoff;
    const __nv_bfloat16* Vhi = g_vhi + bhoff;
    const __nv_bfloat16* Vlo = g_vlo + bhoff;
    const float* amaskb = amask + (size_t)b * SEQ;

#pragma unroll
    for (int i = 0; i < 4; i++) {
        int chunk = t + 256 * i;
        int row   = chunk >> 3;
        int ch    = chunk & 7;
        uint32_t soff = SWZ128(row * 128 + ch * 16);
        CP_ASYNC16(sb + soff,         Qhi + (size_t)(qt*128 + row) * HD + ch * 8);
        CP_ASYNC16(sb + 16384 + soff, Qlo + (size_t)(qt*128 + row) * HD + ch * 8);
    }
    const int causal = mask_future[0] != 0;
    const int ntiles = causal ? (qt * 2 + 2) : (SEQ / AT_KT);
    const int nfull  = causal ? (qt * 2)     : ntiles;

    a_load_stage(sb, 0, Khi, Klo, Vhi, Vlo, amaskb, 0, t);
    a_load_stage(sb, 1, Khi, Klo, Vhi, Vlo, amaskb, AT_KT, t);

    const int r1 = lid >> 2;
    const int gq1 = qt*128 + m0w + r1;
    const int gq2 = gq1 + 8;
    const int cq  = (lid & 3) * 2;

    float m1 = -1e30f, m2 = -1e30f, l1 = 0.0f, l2 = 0.0f;
    float O[8][4];
#pragma unroll
    for (int i = 0; i < 8; i++)
#pragma unroll
        for (int j = 0; j < 4; j++) O[i][j] = 0.0f;

    for (int kt = 0; kt < ntiles; kt++) {
        if (kt < ntiles - 1) { CP_WAIT1(); } else { CP_WAIT0(); }
        __syncthreads();

        const uint32_t st  = sb + AT_Q + (kt & 1) * AT_STGB;
        const uint32_t msk = sb + AT_MSK + (kt & 1) * 256;

        // ---- S = Q K^T (hi/lo 3-product) ----
        float S[8][4];
#pragma unroll
        for (int i = 0; i < 8; i++)
#pragma unroll
            for (int j = 0; j < 4; j++) S[i][j] = 0.0f;

#pragma unroll
        for (int k16 = 0; k16 < 4; k16++) {
            const int colb = k16 * 32 + (lid >> 4) * 16;
            uint32_t qh_[4], ql_[4];
            {
                int row = m0w + (lid & 15);
                uint32_t off = SWZ128(row * 128 + colb);
                LDSM4(qh_[0], qh_[1], qh_[2], qh_[3], sb + off);
                LDSM4(ql_[0], ql_[1], ql_[2], ql_[3], sb + 16384 + off);
            }
#pragma unroll
            for (int np = 0; np < 4; np++) {
                int row = np * 16 + (lid & 15);
                uint32_t off = SWZ128(row * 128 + colb);
                uint32_t kh_[4], kl_[4];
                LDSM4(kh_[0], kh_[1], kh_[2], kh_[3], st + off);
                LDSM4(kl_[0], kl_[1], kl_[2], kl_[3], st + 8192 + off);
                mma16816(S[2*np],   qh_, kh_[0], kh_[2]);
                mma16816(S[2*np],   qh_, kl_[0], kl_[2]);
                mma16816(S[2*np],   ql_, kh_[0], kh_[2]);
                mma16816(S[2*np+1], qh_, kh_[1], kh_[3]);
                mma16816(S[2*np+1], qh_, kl_[1], kl_[3]);
                mma16816(S[2*np+1], ql_, kh_[1], kh_[3]);
            }
        }

        // ---- scale + masks ----
        const int diag = (kt >= nfull);
#pragma unroll
        for (int nt = 0; nt < 8; nt++) {
            int jl0 = nt * 8 + cq;
            float p0, p1;
            asm("ld.shared.f32 %0, [%1];" : "=f"(p0) : "r"(msk + jl0 * 4));
            asm("ld.shared.f32 %0, [%1];" : "=f"(p1) : "r"(msk + jl0 * 4 + 4));
            int gk0 = kt * AT_KT + jl0;
#pragma unroll
            for (int c = 0; c < 4; c++) {
                float sv = S[nt][c] * 0.125f;
                int gk = gk0 + (c & 1);
                int gq = (c < 2) ? gq1 : gq2;
                if (diag && gk > gq) sv += NEGBIAS;
                float pm = (c & 1) ? p1 : p0;
                if (pm == 0.0f) sv = NEGBIAS;
                S[nt][c] = sv;
            }
        }

        // ---- online softmax ----
        float t1 = -1e30f, t2 = -1e30f;
#pragma unroll
        for (int nt = 0; nt < 8; nt++) {
            t1 = fmaxf(t1, fmaxf(S[nt][0], S[nt][1]));
            t2 = fmaxf(t2, fmaxf(S[nt][2], S[nt][3]));
        }
        t1 = fmaxf(t1, __shfl_xor_sync(0xffffffffu, t1, 1));
        t1 = fmaxf(t1, __shfl_xor_sync(0xffffffffu, t1, 2));
        t2 = fmaxf(t2, __shfl_xor_sync(0xffffffffu, t2, 1));
        t2 = fmaxf(t2, __shfl_xor_sync(0xffffffffu, t2, 2));
        float mn1 = fmaxf(m1, t1), mn2 = fmaxf(m2, t2);
        float corr1 = __expf(m1 - mn1), corr2 = __expf(m2 - mn2);
        m1 = mn1; m2 = mn2;
        l1 *= corr1; l2 *= corr2;

        uint32_t phi[4][4], plo[4][4];
#pragma unroll
        for (int nt2 = 0; nt2 < 4; nt2++) {
#pragma unroll
            for (int half = 0; half < 2; half++) {
                int nt = 2*nt2 + half;
                float e0 = __expf(S[nt][0] - mn1);
                float e1 = __expf(S[nt][1] - mn1);
                float e2 = __expf(S[nt][2] - mn2);
                float e3 = __expf(S[nt][3] - mn2);
                l1 += e0 + e1; l2 += e2 + e3;
                uint16_t hh0, ll0, hh1, ll1, hh2, ll2, hh3, ll3;
                split1(e0, hh0, ll0); split1(e1, hh1, ll1);
                split1(e2, hh2, ll2); split1(e3, hh3, ll3);
                phi[nt2][2*half]   = (uint32_t)hh0 | ((uint32_t)hh1 << 16);
                phi[nt2][2*half+1] = (uint32_t)hh2 | ((uint32_t)hh3 << 16);
                plo[nt2][2*half]   = (uint32_t)ll0 | ((uint32_t)ll1 << 16);
                plo[nt2][2*half+1] = (uint32_t)ll2 | ((uint32_t)ll3 << 16);
            }
        }

        // rescale O
#pragma unroll
        for (int i = 0; i < 8; i++) {
            O[i][0] *= corr1; O[i][1] *= corr1;
            O[i][2] *= corr2; O[i][3] *= corr2;
        }

        // ---- O += P V (hi/lo 3-product) ----
        const uint32_t vbase_hi = st + 16384, vbase_lo = st + 24576;
#pragma unroll
        for (int hdb = 0; hdb < 4; hdb++) {
#pragma unroll
            for (int k16 = 0; k16 < 4; k16++) {
                int row  = k16 * 16 + (lid & 7) + ((lid >> 3) & 1) * 8;
                int colb = hdb * 32 + (lid >> 4) * 16;
                uint32_t off = SWZ128(row * 128 + colb);
                uint32_t vh_[4], vl_[4];
                LDSM4T(vh_[0], vh_[1], vh_[2], vh_[3], vbase_hi + off);
                LDSM4T(vl_[0], vl_[1], vl_[2], vl_[3], vbase_lo + off);
                mma16816(O[2*hdb],   phi[k16], vh_[0], vh_[1]);
                mma16816(O[2*hdb],   phi[k16], vl_[0], vl_[1]);
                mma16816(O[2*hdb],   plo[k16], vh_[0], vh_[1]);
                mma16816(O[2*hdb+1], phi[k16], vh_[2], vh_[3]);
                mma16816(O[2*hdb+1], phi[k16], vl_[2], vl_[3]);
                mma16816(O[2*hdb+1], plo[k16], vh_[2], vh_[3]);
            }
        }

        __syncthreads();
        if (kt + 2 < ntiles)
            a_load_stage(sb, kt & 1, Khi, Klo, Vhi, Vlo, amaskb, (kt + 2) * AT_KT, t);
    }

    // finalize l across quad
    l1 += __shfl_xor_sync(0xffffffffu, l1, 1);
    l1 += __shfl_xor_sync(0xffffffffu, l1, 2);
    l2 += __shfl_xor_sync(0xffffffffu, l2, 1);
    l2 += __shfl_xor_sync(0xffffffffu, l2, 2);
    float rl1 = 1.0f / l1, rl2 = 1.0f / l2;

    const size_t rowb1 = ((size_t)b * SEQ + gq1) * DM + h * HD;
    const size_t rowb2 = ((size_t)b * SEQ + gq2) * DM + h * HD;
#pragma unroll
    for (int nt = 0; nt < 8; nt++) {
        int col = nt * 8 + cq;
        float v0 = O[nt][0] * rl1, v1 = O[nt][1] * rl1;
        float v2 = O[nt][2] * rl2, v3 = O[nt][3] * rl2;
        uint16_t h0, l0, h1b, l1b, h2, l2b, h3, l3;
        split1(v0, h0, l0); split1(v1, h1b, l1b);
        split1(v2, h2, l2b); split1(v3, h3, l3);
        *(uint32_t*)&g_xhi[rowb1 + col] = (uint32_t)h0 | ((uint32_t)h1b << 16);
        *(uint32_t*)&g_xlo[rowb1 + col] = (uint32_t)l0 | ((uint32_t)l1b << 16);
        *(uint32_t*)&g_xhi[rowb2 + col] = (uint32_t)h2 | ((uint32_t)h3 << 16);
        *(uint32_t*)&g_xlo[rowb2 + col] = (uint32_t)l2b | ((uint32_t)l3 << 16);
    }
}

// ---------------------------------------------------------------------------
extern "C" void kernel_launch(void* const* d_in, const int* in_sizes, int n_in,
                              void* d_out, int out_size)
{
    const float* q  = (const float*)d_in[0];
    const float* k  = (const float*)d_in[1];
    const float* v  = (const float*)d_in[2];
    const float* am = (const float*)d_in[3];
    const float* Wq = (const float*)d_in[4];
    const float* Wk = (const float*)d_in[5];
    const float* Wv = (const float*)d_in[6];
    const float* Wo = (const float*)d_in[7];
    const int*   mf = (const int*)  d_in[8];
    float* out = (float*)d_out;

    __nv_bfloat16 *xhi, *xlo, *whi, *wlo;
    cudaGetSymbolAddress((void**)&xhi, g_xhi);
    cudaGetSymbolAddress((void**)&xlo, g_xlo);
    cudaGetSymbolAddress((void**)&whi, g_whi);
    cudaGetSymbolAddress((void**)&wlo, g_wlo);

    static bool attr_set = false;
    if (!attr_set) {
        cudaFuncSetAttribute(gemm_hmma,
                             cudaFuncAttributeMaxDynamicSharedMemorySize, GSMEM_BYTES);
        cudaFuncSetAttribute(attn_hmma,
                             cudaFuncAttributeMaxDynamicSharedMemorySize, ATTN_SMEM_BYTES);
        attr_set = true;
    }

    split_acts<<<dim3(MROWS*DM/4/256, 3), 256>>>((const float4*)q, (const float4*)k,
                                                 (const float4*)v);
    split_w<<<dim3(DM*DM/4/256, 4), 256>>>((const float4*)Wq, (const float4*)Wk,
                                           (const float4*)Wv, (const float4*)Wo);

    gemm_hmma<<<dim3(DM/128, MROWS/128, 3), 256, GSMEM_BYTES>>>(
        xhi, xlo, whi, wlo, nullptr);

    attn_hmma<<<dim3(SEQ/128, BATCH*NH), 256, ATTN_SMEM_BYTES>>>(am, mf);

    gemm_hmma<<<dim3(DM/128, MROWS/128, 1), 256, GSMEM_BYTES>>>(
        xhi, xlo, whi + (size_t)3*DM*DM, wlo + (size_t)3*DM*DM, out);
}

// round 12
// speedup vs baseline: 1.2173x; 1.1445x over previous
#include <cuda_runtime.h>
#include <cuda_bf16.h>
#include <cuda_fp16.h>
#include <cstdint>

// Problem constants
#define BATCH 4
#define SEQ   2048
#define DM    1024
#define NH    16
#define HD    64
#define MROWS (BATCH*SEQ)          // 8192
#define NEGBIAS (-10000.0f)

// Scratch (no allocation allowed)
__device__ __nv_bfloat16 g_qhi[BATCH*NH*SEQ*HD];
__device__ __nv_bfloat16 g_qlo[BATCH*NH*SEQ*HD];
__device__ __nv_bfloat16 g_khi[BATCH*NH*SEQ*HD];
__device__ __nv_bfloat16 g_klo[BATCH*NH*SEQ*HD];
__device__ __nv_bfloat16 g_vhi[BATCH*NH*SEQ*HD];   // V stored as fp16 (single)
__device__ __nv_bfloat16 g_xhi[3*MROWS*DM];
__device__ __nv_bfloat16 g_xlo[3*MROWS*DM];
__device__ __nv_bfloat16 g_whi[4*DM*DM];
__device__ __nv_bfloat16 g_wlo[4*DM*DM];
__device__ float g_bias[BATCH*SEQ];                // mask -> additive bias

// ---------------------------------------------------------------------------
// helpers
// ---------------------------------------------------------------------------
__device__ __forceinline__ uint32_t smem_u32(const void* p) {
    uint32_t a;
    asm("{ .reg .u64 t; cvta.to.shared.u64 t, %1; cvt.u32.u64 %0, t; }" : "=r"(a) : "l"(p));
    return a;
}
#define SWZ128(o) ((uint32_t)(o) ^ ((((uint32_t)(o)) >> 3) & 0x70))

#define CP_ASYNC16(saddr, gptr) \
    asm volatile("cp.async.cg.shared.global [%0], [%1], 16;" :: "r"(saddr), "l"(gptr) : "memory")
#define CP_ASYNC4(saddr, gptr) \
    asm volatile("cp.async.ca.shared.global [%0], [%1], 4;" :: "r"(saddr), "l"(gptr) : "memory")
#define CP_COMMIT() asm volatile("cp.async.commit_group;" ::: "memory")
#define CP_WAIT1()  asm volatile("cp.async.wait_group 1;" ::: "memory")
#define CP_WAIT0()  asm volatile("cp.async.wait_group 0;" ::: "memory")

#define LDSM4(R0,R1,R2,R3,ADDR) \
    asm volatile("ldmatrix.sync.aligned.m8n8.x4.shared.b16 {%0,%1,%2,%3}, [%4];" \
        : "=r"(R0), "=r"(R1), "=r"(R2), "=r"(R3) : "r"(ADDR))
#define LDSM4T(R0,R1,R2,R3,ADDR) \
    asm volatile("ldmatrix.sync.aligned.m8n8.x4.trans.shared.b16 {%0,%1,%2,%3}, [%4];" \
        : "=r"(R0), "=r"(R1), "=r"(R2), "=r"(R3) : "r"(ADDR))

__device__ __forceinline__ void mma16816(float* c, const uint32_t* a,
                                         uint32_t b0, uint32_t b1) {
    asm volatile(
        "mma.sync.aligned.m16n8k16.row.col.f32.bf16.bf16.f32 "
        "{%0,%1,%2,%3}, {%4,%5,%6,%7}, {%8,%9}, {%0,%1,%2,%3};"
        : "+f"(c[0]), "+f"(c[1]), "+f"(c[2]), "+f"(c[3])
        : "r"(a[0]), "r"(a[1]), "r"(a[2]), "r"(a[3]), "r"(b0), "r"(b1));
}
__device__ __forceinline__ void mma16816f(float* c, const uint32_t* a,
                                          uint32_t b0, uint32_t b1) {
    asm volatile(
        "mma.sync.aligned.m16n8k16.row.col.f32.f16.f16.f32 "
        "{%0,%1,%2,%3}, {%4,%5,%6,%7}, {%8,%9}, {%0,%1,%2,%3};"
        : "+f"(c[0]), "+f"(c[1]), "+f"(c[2]), "+f"(c[3])
        : "r"(a[0]), "r"(a[1]), "r"(a[2]), "r"(a[3]), "r"(b0), "r"(b1));
}

__device__ __forceinline__ void split1(float v, uint16_t& hi, uint16_t& lo) {
    __nv_bfloat16 bh = __float2bfloat16(v);
    hi = __bfloat16_as_ushort(bh);
    lo = __bfloat16_as_ushort(__float2bfloat16(v - __bfloat162float(bh)));
}
__device__ __forceinline__ uint32_t packh2(float a, float b) {
    __half2 h = __floats2half2_rn(a, b);
    return *(uint32_t*)&h;
}

// ---------------------------------------------------------------------------
// split + preprocessing kernels
// ---------------------------------------------------------------------------
__device__ __forceinline__ void split4(const float4* src, uint2* hi, uint2* lo, int i) {
    float4 v = src[i];
    float f[4] = {v.x, v.y, v.z, v.w};
    uint32_t h[4], l[4];
#pragma unroll
    for (int j = 0; j < 4; j++) {
        uint16_t hb, lb;
        split1(f[j], hb, lb);
        h[j] = hb; l[j] = lb;
    }
    hi[i] = make_uint2(h[0] | (h[1] << 16), h[2] | (h[3] << 16));
    lo[i] = make_uint2(l[0] | (l[1] << 16), l[2] | (l[3] << 16));
}

__global__ void __launch_bounds__(256)
split_acts(const float4* __restrict__ q, const float4* __restrict__ k,
           const float4* __restrict__ v)
{
    const int sel = blockIdx.y;
    const int n4  = MROWS * DM / 4;
    int i = blockIdx.x * 256 + threadIdx.x;
    if (i >= n4) return;
    const float4* src = (sel == 0) ? q : (sel == 1) ? k : v;
    uint2* hi = (uint2*)&g_xhi[(size_t)sel * MROWS * DM];
    uint2* lo = (uint2*)&g_xlo[(size_t)sel * MROWS * DM];
    split4(src, hi, lo, i);
}

__global__ void __launch_bounds__(256)
split_w(const float4* __restrict__ wq, const float4* __restrict__ wk,
        const float4* __restrict__ wv, const float4* __restrict__ wo)
{
    const int sel = blockIdx.y;
    const int n4  = DM * DM / 4;
    int i = blockIdx.x * 256 + threadIdx.x;
    if (i >= n4) return;
    const float4* src = (sel == 0) ? wq : (sel == 1) ? wk : (sel == 2) ? wv : wo;
    uint2* hi = (uint2*)&g_whi[(size_t)sel * DM * DM];
    uint2* lo = (uint2*)&g_wlo[(size_t)sel * DM * DM];
    split4(src, hi, lo, i);
}

__global__ void __launch_bounds__(256)
mask_bias(const float* __restrict__ amask)
{
    int i = blockIdx.x * 256 + threadIdx.x;
    if (i < BATCH*SEQ)
        g_bias[i] = (amask[i] == 0.0f) ? NEGBIAS : 0.0f;
}

// ---------------------------------------------------------------------------
// HMMA GEMM, BK=32, hi|lo packed in 128-byte smem rows, 3 stages (96 KB),
// 2 CTAs/SM. (unchanged from R9 except V epilogue writes fp16 single)
// ---------------------------------------------------------------------------
#define GT_STAGE 32768
#define GSTAGES  3
#define GSMEM_BYTES (GSTAGES*GT_STAGE)   // 96 KB
#define NCHUNK 32                        // K=1024 / 32

__device__ __forceinline__ void g_load_stage(
    uint32_t sb, int stage,
    const __nv_bfloat16* __restrict__ Ahi, const __nv_bfloat16* __restrict__ Alo,
    const __nv_bfloat16* __restrict__ Bhi, const __nv_bfloat16* __restrict__ Blo,
    int m0, int n0, int k0, int t)
{
    const uint32_t base = sb + stage * GT_STAGE;
#pragma unroll
    for (int i = 0; i < 8; i++) {
        int idx = t + 256 * i;              // 0..2047
        int mat = idx >> 10;                // 0=A, 1=B
        int r   = (idx >> 3) & 127;
        int c   = idx & 7;                  // 0-3 hi, 4-7 lo
        uint32_t soff = (uint32_t)mat * 16384 + SWZ128(r * 128 + c * 16);
        const __nv_bfloat16* src;
        int gcol = k0 + (c & 3) * 8;
        if (mat == 0) src = ((c < 4) ? Ahi : Alo) + (size_t)(m0 + r) * DM + gcol;
        else          src = ((c < 4) ? Bhi : Blo) + (size_t)(n0 + r) * DM + gcol;
        CP_ASYNC16(base + soff, src);
    }
    CP_COMMIT();
}

__global__ void __launch_bounds__(256, 2)
gemm_hmma(const __nv_bfloat16* __restrict__ Ahi_, const __nv_bfloat16* __restrict__ Alo_,
          const __nv_bfloat16* __restrict__ Bhi_, const __nv_bfloat16* __restrict__ Blo_,
          float* __restrict__ outf)
{
    extern __shared__ char smem[];
    const uint32_t sb = smem_u32(smem);
    const int t   = threadIdx.x;
    const int wid = t >> 5, lid = t & 31;
    const int wm  = wid & 3;
    const int wn  = wid >> 2;
    const int m0  = blockIdx.y * 128;
    const int n0  = blockIdx.x * 128;
    const int z   = blockIdx.z;

    const __nv_bfloat16* Ahi = Ahi_ + (size_t)z * MROWS * DM;
    const __nv_bfloat16* Alo = Alo_ + (size_t)z * MROWS * DM;
    const __nv_bfloat16* Bhi = Bhi_ + (size_t)z * DM * DM;
    const __nv_bfloat16* Blo = Blo_ + (size_t)z * DM * DM;

    float acc[2][8][4];
#pragma unroll
    for (int a = 0; a < 2; a++)
#pragma unroll
        for (int b = 0; b < 8; b++)
#pragma unroll
            for (int c = 0; c < 4; c++) acc[a][b][c] = 0.0f;

    g_load_stage(sb, 0, Ahi, Alo, Bhi, Blo, m0, n0, 0,  t);
    g_load_stage(sb, 1, Ahi, Alo, Bhi, Blo, m0, n0, 32, t);

    for (int c = 0; c < NCHUNK; c++) {
        if (c < NCHUNK - 1) { CP_WAIT1(); } else { CP_WAIT0(); }
        __syncthreads();
        if (c + 2 < NCHUNK)
            g_load_stage(sb, (c + 2) % GSTAGES, Ahi, Alo, Bhi, Blo, m0, n0, (c + 2) * 32, t);

        const uint32_t st = sb + (c % GSTAGES) * GT_STAGE;
#pragma unroll
        for (int ks = 0; ks < 2; ks++) {
            const int cb = ks * 32 + ((lid >> 4) << 4);
            uint32_t ah[2][4], al[2][4];
#pragma unroll
            for (int mt = 0; mt < 2; mt++) {
                int row = wm * 32 + mt * 16 + (lid & 15);
                LDSM4(ah[mt][0], ah[mt][1], ah[mt][2], ah[mt][3],
                      st + SWZ128(row * 128 + cb));
                LDSM4(al[mt][0], al[mt][1], al[mt][2], al[mt][3],
                      st + SWZ128(row * 128 + 64 + cb));
            }
#pragma unroll
            for (int np = 0; np < 4; np++) {
                int row = wn * 64 + np * 16 + (lid & 15);
                uint32_t bh[4], bl[4];
                LDSM4(bh[0], bh[1], bh[2], bh[3], st + 16384 + SWZ128(row * 128 + cb));
                LDSM4(bl[0], bl[1], bl[2], bl[3], st + 16384 + SWZ128(row * 128 + 64 + cb));
#pragma unroll
                for (int mt = 0; mt < 2; mt++) {
                    mma16816(acc[mt][2*np],   ah[mt], bh[0], bh[2]);
                    mma16816(acc[mt][2*np],   ah[mt], bl[0], bl[2]);
                    mma16816(acc[mt][2*np],   al[mt], bh[0], bh[2]);
                    mma16816(acc[mt][2*np+1], ah[mt], bh[1], bh[3]);
                    mma16816(acc[mt][2*np+1], ah[mt], bl[1], bl[3]);
                    mma16816(acc[mt][2*np+1], al[mt], bh[1], bh[3]);
                }
            }
        }
    }

    // epilogue
    __nv_bfloat16* ohi = nullptr;
    __nv_bfloat16* olo = nullptr;
    if (!outf) {
        ohi = (z == 0) ? g_qhi : (z == 1) ? g_khi : g_vhi;
        olo = (z == 0) ? g_qlo : (z == 1) ? g_klo : nullptr;
    }
#pragma unroll
    for (int mt = 0; mt < 2; mt++) {
#pragma unroll
        for (int nt = 0; nt < 8; nt++) {
            int row0 = m0 + wm * 32 + mt * 16 + (lid >> 2);
            int col  = n0 + wn * 64 + nt * 8 + (lid & 3) * 2;
#pragma unroll
            for (int half = 0; half < 2; half++) {
                int row = row0 + half * 8;
                float vx = acc[mt][nt][half * 2 + 0];
                float vy = acc[mt][nt][half * 2 + 1];
                if (!outf) {
                    int bb = row >> 11, tt2 = row & 2047;
                    int h = col >> 6, dh = col & 63;
                    size_t base = ((((size_t)bb * NH + h) * SEQ) + tt2) * HD + dh;
                    if (z == 2) {
                        // V: single fp16
                        *(uint32_t*)&ohi[base] = packh2(vx, vy);
                    } else {
                        uint16_t hx, lx, hy, ly;
                        split1(vx, hx, lx);
                        split1(vy, hy, ly);
                        *(uint32_t*)&ohi[base] = (uint32_t)hx | ((uint32_t)hy << 16);
                        *(uint32_t*)&olo[base] = (uint32_t)lx | ((uint32_t)ly << 16);
                    }
                } else {
                    float2 v2; v2.x = vx; v2.y = vy;
                    *(float2*)&outf[(size_t)row * DM + col] = v2;
                }
            }
        }
    }
}

// ---------------------------------------------------------------------------
// HMMA flash attention. QK: bf16 hi/lo 3-product. PV: fp16 P x fp16 V, 1 product.
// 3-stage pipeline, 24KB/stage -> 107KB smem -> 2 CTAs/SM.
// Stage: Khi 8K | Klo 8K | Vf16 8K. Longest-first causal order.
// ---------------------------------------------------------------------------
#define AT_KT     64
#define AT_Q      32768
#define AT_STGB   24576
#define AT_STAGES 3
#define AT_MSK    (AT_Q + AT_STAGES*AT_STGB)   // 106496
#define ATTN_SMEM_BYTES (AT_MSK + AT_STAGES*256)

__device__ __forceinline__ void a_load_stage(
    uint32_t sb, int stage,
    const __nv_bfloat16* Khi, const __nv_bfloat16* Klo,
    const __nv_bfloat16* Vf16,
    const float* biasb, int kt0, int t)
{
    const uint32_t base = sb + AT_Q + stage * AT_STGB;
#pragma unroll
    for (int i = 0; i < 6; i++) {
        int chunk = t + 256 * i;            // 0..1535
        int tsel  = chunk >> 9;             // 0=Khi, 1=Klo, 2=V
        int c     = chunk & 511;
        int row   = c >> 3;
        int ch    = c & 7;
        uint32_t soff = (uint32_t)tsel * 8192 + SWZ128(row * 128 + ch * 16);
        const __nv_bfloat16* src =
            (tsel == 0) ? Khi : (tsel == 1) ? Klo : Vf16;
        CP_ASYNC16(base + soff, src + (size_t)(kt0 + row) * HD + ch * 8);
    }
    if (t < AT_KT)
        CP_ASYNC4(sb + AT_MSK + stage * 256 + t * 4, biasb + kt0 + t);
    CP_COMMIT();
}

__global__ void __launch_bounds__(256, 2)
attn_hmma(const int* __restrict__ mask_future)
{
    extern __shared__ char smem[];
    const uint32_t sb = smem_u32(smem);
    const int t   = threadIdx.x;
    const int wid = t >> 5, lid = t & 31;
    const int bh  = blockIdx.y;
    const int b   = bh >> 4;
    const int h   = bh & 15;
    const int qt  = gridDim.x - 1 - blockIdx.x;   // longest tiles first
    const int m0w = wid * 16;

    const size_t bhoff = (size_t)bh * SEQ * HD;
    const __nv_bfloat16* Qhi  = g_qhi + bhoff;
    const __nv_bfloat16* Qlo  = g_qlo + bhoff;
    const __nv_bfloat16* Khi  = g_khi + bhoff;
    const __nv_bfloat16* Klo  = g_klo + bhoff;
    const __nv_bfloat16* Vf16 = g_vhi + bhoff;
    const float* biasb = g_bias + (size_t)b * SEQ;

#pragma unroll
    for (int i = 0; i < 4; i++) {
        int chunk = t + 256 * i;
        int row   = chunk >> 3;
        int ch    = chunk & 7;
        uint32_t soff = SWZ128(row * 128 + ch * 16);
        CP_ASYNC16(sb + soff,         Qhi + (size_t)(qt*128 + row) * HD + ch * 8);
        CP_ASYNC16(sb + 16384 + soff, Qlo + (size_t)(qt*128 + row) * HD + ch * 8);
    }
    const int causal = mask_future[0] != 0;
    const int ntiles = causal ? (qt * 2 + 2) : (SEQ / AT_KT);
    const int nfull  = causal ? (qt * 2)     : ntiles;

    a_load_stage(sb, 0, Khi, Klo, Vf16, biasb, 0, t);
    a_load_stage(sb, 1, Khi, Klo, Vf16, biasb, AT_KT, t);

    const int r1 = lid >> 2;
    const int gq1 = qt*128 + m0w + r1;
    const int gq2 = gq1 + 8;
    const int cq  = (lid & 3) * 2;

    float m1 = -1e30f, m2 = -1e30f, l1 = 0.0f, l2 = 0.0f;
    float O[8][4];
#pragma unroll
    for (int i = 0; i < 8; i++)
#pragma unroll
        for (int j = 0; j < 4; j++) O[i][j] = 0.0f;

    for (int kt = 0; kt < ntiles; kt++) {
        if (kt < ntiles - 1) { CP_WAIT1(); } else { CP_WAIT0(); }
        __syncthreads();
        if (kt + 2 < ntiles)
            a_load_stage(sb, (kt + 2) % AT_STAGES, Khi, Klo, Vf16, biasb,
                         (kt + 2) * AT_KT, t);

        const uint32_t st  = sb + AT_Q + (kt % AT_STAGES) * AT_STGB;
        const uint32_t msk = sb + AT_MSK + (kt % AT_STAGES) * 256;

        // ---- S = Q K^T (bf16 hi/lo 3-product) ----
        float S[8][4];
#pragma unroll
        for (int i = 0; i < 8; i++)
#pragma unroll
            for (int j = 0; j < 4; j++) S[i][j] = 0.0f;

#pragma unroll
        for (int k16 = 0; k16 < 4; k16++) {
            const int colb = k16 * 32 + (lid >> 4) * 16;
            uint32_t qh_[4], ql_[4];
            {
                int row = m0w + (lid & 15);
                uint32_t off = SWZ128(row * 128 + colb);
                LDSM4(qh_[0], qh_[1], qh_[2], qh_[3], sb + off);
                LDSM4(ql_[0], ql_[1], ql_[2], ql_[3], sb + 16384 + off);
            }
#pragma unroll
            for (int np = 0; np < 4; np++) {
                int row = np * 16 + (lid & 15);
                uint32_t off = SWZ128(row * 128 + colb);
                uint32_t kh_[4], kl_[4];
                LDSM4(kh_[0], kh_[1], kh_[2], kh_[3], st + off);
                LDSM4(kl_[0], kl_[1], kl_[2], kl_[3], st + 8192 + off);
                mma16816(S[2*np],   qh_, kh_[0], kh_[2]);
                mma16816(S[2*np],   qh_, kl_[0], kl_[2]);
                mma16816(S[2*np],   ql_, kh_[0], kh_[2]);
                mma16816(S[2*np+1], qh_, kh_[1], kh_[3]);
                mma16816(S[2*np+1], qh_, kl_[1], kl_[3]);
                mma16816(S[2*np+1], ql_, kh_[1], kh_[3]);
            }
        }

        // ---- scale + bias masks ----
        const int diag = (kt >= nfull);
#pragma unroll
        for (int nt = 0; nt < 8; nt++) {
            int jl0 = nt * 8 + cq;
            float b0, b1;
            asm("ld.shared.f32 %0, [%1];" : "=f"(b0) : "r"(msk + jl0 * 4));
            asm("ld.shared.f32 %0, [%1];" : "=f"(b1) : "r"(msk + jl0 * 4 + 4));
            int gk0 = kt * AT_KT + jl0;
#pragma unroll
            for (int c = 0; c < 4; c++) {
                float sv = fmaf(S[nt][c], 0.125f, (c & 1) ? b1 : b0);
                if (diag) {
                    int gk = gk0 + (c & 1);
                    int gq = (c < 2) ? gq1 : gq2;
                    if (gk > gq) sv += NEGBIAS;
                }
                S[nt][c] = sv;
            }
        }

        // ---- online softmax ----
        float t1 = -1e30f, t2 = -1e30f;
#pragma unroll
        for (int nt = 0; nt < 8; nt++) {
            t1 = fmaxf(t1, fmaxf(S[nt][0], S[nt][1]));
            t2 = fmaxf(t2, fmaxf(S[nt][2], S[nt][3]));
        }
        t1 = fmaxf(t1, __shfl_xor_sync(0xffffffffu, t1, 1));
        t1 = fmaxf(t1, __shfl_xor_sync(0xffffffffu, t1, 2));
        t2 = fmaxf(t2, __shfl_xor_sync(0xffffffffu, t2, 1));
        t2 = fmaxf(t2, __shfl_xor_sync(0xffffffffu, t2, 2));
        float mn1 = fmaxf(m1, t1), mn2 = fmaxf(m2, t2);
        float corr1 = __expf(m1 - mn1), corr2 = __expf(m2 - mn2);
        m1 = mn1; m2 = mn2;
        l1 *= corr1; l2 *= corr2;

        // P as packed fp16 A-frags
        uint32_t pf[4][4];
#pragma unroll
        for (int nt2 = 0; nt2 < 4; nt2++) {
#pragma unroll
            for (int half = 0; half < 2; half++) {
                int nt = 2*nt2 + half;
                float e0 = __expf(S[nt][0] - mn1);
                float e1 = __expf(S[nt][1] - mn1);
                float e2 = __expf(S[nt][2] - mn2);
                float e3 = __expf(S[nt][3] - mn2);
                l1 += e0 + e1; l2 += e2 + e3;
                pf[nt2][2*half]   = packh2(e0, e1);
                pf[nt2][2*half+1] = packh2(e2, e3);
            }
        }

        // rescale O
#pragma unroll
        for (int i = 0; i < 8; i++) {
            O[i][0] *= corr1; O[i][1] *= corr1;
            O[i][2] *= corr2; O[i][3] *= corr2;
        }

        // ---- O += P V (fp16 single product) ----
        const uint32_t vbase = st + 16384;
#pragma unroll
        for (int hdb = 0; hdb < 4; hdb++) {
#pragma unroll
            for (int k16 = 0; k16 < 4; k16++) {
                int row  = k16 * 16 + (lid & 7) + ((lid >> 3) & 1) * 8;
                int colb = hdb * 32 + (lid >> 4) * 16;
                uint32_t off = SWZ128(row * 128 + colb);
                uint32_t vh_[4];
                LDSM4T(vh_[0], vh_[1], vh_[2], vh_[3], vbase + off);
                mma16816f(O[2*hdb],   pf[k16], vh_[0], vh_[1]);
                mma16816f(O[2*hdb+1], pf[k16], vh_[2], vh_[3]);
            }
        }
    }

    // finalize l across quad
    l1 += __shfl_xor_sync(0xffffffffu, l1, 1);
    l1 += __shfl_xor_sync(0xffffffffu, l1, 2);
    l2 += __shfl_xor_sync(0xffffffffu, l2, 1);
    l2 += __shfl_xor_sync(0xffffffffu, l2, 2);
    float rl1 = 1.0f / l1, rl2 = 1.0f / l2;

    const size_t rowb1 = ((size_t)b * SEQ + gq1) * DM + h * HD;
    const size_t rowb2 = ((size_t)b * SEQ + gq2) * DM + h * HD;
#pragma unroll
    for (int nt = 0; nt < 8; nt++) {
        int col = nt * 8 + cq;
        float v0 = O[nt][0] * rl1, v1 = O[nt][1] * rl1;
        float v2 = O[nt][2] * rl2, v3 = O[nt][3] * rl2;
        uint16_t h0, l0, h1b, l1b, h2, l2b, h3, l3;
        split1(v0, h0, l0); split1(v1, h1b, l1b);
        split1(v2, h2, l2b); split1(v3, h3, l3);
        *(uint32_t*)&g_xhi[rowb1 + col] = (uint32_t)h0 | ((uint32_t)h1b << 16);
        *(uint32_t*)&g_xlo[rowb1 + col] = (uint32_t)l0 | ((uint32_t)l1b << 16);
        *(uint32_t*)&g_xhi[rowb2 + col] = (uint32_t)h2 | ((uint32_t)h3 << 16);
        *(uint32_t*)&g_xlo[rowb2 + col] = (uint32_t)l2b | ((uint32_t)l3 << 16);
    }
}

// ---------------------------------------------------------------------------
extern "C" void kernel_launch(void* const* d_in, const int* in_sizes, int n_in,
                              void* d_out, int out_size)
{
    const float* q  = (const float*)d_in[0];
    const float* k  = (const float*)d_in[1];
    const float* v  = (const float*)d_in[2];
    const float* am = (const float*)d_in[3];
    const float* Wq = (const float*)d_in[4];
    const float* Wk = (const float*)d_in[5];
    const float* Wv = (const float*)d_in[6];
    const float* Wo = (const float*)d_in[7];
    const int*   mf = (const int*)  d_in[8];
    float* out = (float*)d_out;

    __nv_bfloat16 *xhi, *xlo, *whi, *wlo;
    cudaGetSymbolAddress((void**)&xhi, g_xhi);
    cudaGetSymbolAddress((void**)&xlo, g_xlo);
    cudaGetSymbolAddress((void**)&whi, g_whi);
    cudaGetSymbolAddress((void**)&wlo, g_wlo);

    static bool attr_set = false;
    if (!attr_set) {
        cudaFuncSetAttribute(gemm_hmma,
                             cudaFuncAttributeMaxDynamicSharedMemorySize, GSMEM_BYTES);
        cudaFuncSetAttribute(attn_hmma,
                             cudaFuncAttributeMaxDynamicSharedMemorySize, ATTN_SMEM_BYTES);
        attr_set = true;
    }

    split_acts<<<dim3(MROWS*DM/4/256, 3), 256>>>((const float4*)q, (const float4*)k,
                                                 (const float4*)v);
    split_w<<<dim3(DM*DM/4/256, 4), 256>>>((const float4*)Wq, (const float4*)Wk,
                                           (const float4*)Wv, (const float4*)Wo);
    mask_bias<<<BATCH*SEQ/256, 256>>>(am);

    gemm_hmma<<<dim3(DM/128, MROWS/128, 3), 256, GSMEM_BYTES>>>(
        xhi, xlo, whi, wlo, nullptr);

    attn_hmma<<<dim3(SEQ/128, BATCH*NH), 256, ATTN_SMEM_BYTES>>>(mf);

    gemm_hmma<<<dim3(DM/128, MROWS/128, 1), 256, GSMEM_BYTES>>>(
        xhi, xlo, whi + (size_t)3*DM*DM, wlo + (size_t)3*DM*DM, out);
}